// round 7
// baseline (speedup 1.0000x reference)
#include <cuda_runtime.h>

// Motion loss: loss_rot + loss_fk + loss_pos.
// B=64, T=2048, J=24, C=4*J+3=99.
//
// One thread per (b,t). Both motions (Y,X) ride the two lanes of packed f32x2
// registers: quat2mat / mm33 / mv3 execute as FFMA2/FADD2/FMUL2, halving the
// fma-pipe instruction count vs scalar (R4 evidence: kernel is issue-bound,
// not occupancy-bound). No shuffles (R6 evidence: SHFL burned the MIO pipe).
// FK state kept in registers via a 3-slot pool (topology liveness).
// Two-kernel reduction (measured faster than fused threadfence tail).

#define NB 64
#define NT 2048
#define NJ 24
#define NC 99

#define TPB 128                    // threads per block (t-chunk)
#define GX  (NT / TPB)             // 16
#define NBLK (GX * NB)             // 1024 partial sums
#define RTPB 256                   // reduce kernel threads

__device__ float g_partial[NBLK];

// Slot assignment (A=0,B=1,C=2) from liveness analysis of the chain.
#define PSLOT_INIT {-1,0,0,0,1,2,0,1,2,0,1,2,0,0,0,1,2,0,2,0,2,0,2,0}
#define MSLOT_INIT { 0,1,2,0,1,2,0,1,2,0,-1,-1,1,2,0,-1,2,0,2,0,2,0,-1,-1}

typedef unsigned long long u64;

__device__ __forceinline__ u64 pk(float lo, float hi)
{ u64 r; asm("mov.b64 %0,{%1,%2};" : "=l"(r) : "f"(lo), "f"(hi)); return r; }
__device__ __forceinline__ void upk(u64 v, float& lo, float& hi)
{ asm("mov.b64 {%0,%1},%2;" : "=f"(lo), "=f"(hi) : "l"(v)); }
__device__ __forceinline__ u64 mul2(u64 a, u64 b)
{ u64 r; asm("mul.rn.f32x2 %0,%1,%2;" : "=l"(r) : "l"(a), "l"(b)); return r; }
__device__ __forceinline__ u64 add2(u64 a, u64 b)
{ u64 r; asm("add.rn.f32x2 %0,%1,%2;" : "=l"(r) : "l"(a), "l"(b)); return r; }
__device__ __forceinline__ u64 fma2(u64 a, u64 b, u64 c)
{ u64 r; asm("fma.rn.f32x2 %0,%1,%2,%3;" : "=l"(r) : "l"(a), "l"(b), "l"(c)); return r; }

// packed quat -> rotation matrix (both lanes independent)
__device__ __forceinline__ void quat2mat2(const u64 q[4], u64* m, u64 one2, u64 neg1)
{
    u64 ww = mul2(q[0], q[0]), xx = mul2(q[1], q[1]);
    u64 yy = mul2(q[2], q[2]), zz = mul2(q[3], q[3]);
    u64 n  = add2(add2(ww, xx), add2(yy, zz));
    float nY, nX; upk(n, nY, nX);
    float sY = __fdividef(2.0f, nY), sX = __fdividef(2.0f, nX);
    u64 s  = pk(sY, sX);
    u64 ns = pk(-sY, -sX);
    u64 xy = mul2(q[1], q[2]), xz = mul2(q[1], q[3]), yz = mul2(q[2], q[3]);
    u64 wx = mul2(q[0], q[1]), wy = mul2(q[0], q[2]), wz = mul2(q[0], q[3]);
    m[0] = fma2(ns, add2(yy, zz), one2);
    m[4] = fma2(ns, add2(xx, zz), one2);
    m[8] = fma2(ns, add2(xx, yy), one2);
    m[1] = mul2(s, fma2(wz, neg1, xy));   // s*(xy - wz)
    m[2] = mul2(s, add2(xz, wy));         // s*(xz + wy)
    m[3] = mul2(s, add2(xy, wz));         // s*(xy + wz)
    m[5] = mul2(s, fma2(wx, neg1, yz));   // s*(yz - wx)
    m[6] = mul2(s, fma2(wy, neg1, xz));   // s*(xz - wy)
    m[7] = mul2(s, add2(yz, wx));         // s*(yz + wx)
}

__device__ __forceinline__ void mm33_2(const u64* a, const u64* b, u64* c)
{
#pragma unroll
    for (int i = 0; i < 3; ++i)
#pragma unroll
        for (int j = 0; j < 3; ++j)
            c[i*3 + j] = fma2(a[i*3 + 0], b[0*3 + j],
                         fma2(a[i*3 + 1], b[1*3 + j],
                         mul2(a[i*3 + 2], b[2*3 + j])));
}

__global__ __launch_bounds__(TPB)
void motion_loss_kernel(const float* __restrict__ Ym, const float* __restrict__ Xm,
                        const float* __restrict__ Yt, const float* __restrict__ Xt,
                        const float* __restrict__ jw)
{
    const int b   = blockIdx.y;
    const int tid = threadIdx.x;
    const int t   = blockIdx.x * TPB + tid;

    __shared__ float2 off2[NJ][3];   // (.x = Y-motion, .y = X-motion)
    __shared__ float  ws[NJ];

    if (tid < NJ * 3) {
        off2[tid / 3][tid % 3] = make_float2(Yt[b * NJ * 3 + tid],
                                             Xt[b * NJ * 3 + tid]);
    }
    if (tid < NJ) ws[tid] = jw[tid];
    __syncthreads();

    const float* ymb = Ym + (size_t)b * NC * NT + t;
    const float* xmb = Xm + (size_t)b * NC * NT + t;

    const u64 one2 = pk(1.0f, 1.0f);
    const u64 neg1 = pk(-1.0f, -1.0f);

    float accRot = 0.0f, accFk = 0.0f, accPos = 0.0f;

    u64 T[3][9];    // packed transforms, 3-slot pool
    u64 R[3][3];    // packed world positions

    const int PSLOT[NJ] = PSLOT_INIT;
    const int MSLOT[NJ] = MSLOT_INIT;

#pragma unroll
    for (int j = 0; j < NJ; ++j) {
        const int ps = PSLOT[j];
        const int ms = MSLOT[j];

        u64 q[4];
        float dRot = 0.0f;
#pragma unroll
        for (int k = 0; k < 4; ++k) {
            float qy = __ldcs(&ymb[(size_t)(4*j + k) * NT]);
            float qx = __ldcs(&xmb[(size_t)(4*j + k) * NT]);
            q[k] = pk(qy, qx);
            dRot += fabsf(qy - qx);
        }
        accRot += ws[j] * dRot;

        u64 Rm[9];
        quat2mat2(q, Rm, one2, neg1);

        u64 Tc[9];
        if (ps >= 0) {
            mm33_2(T[ps], Rm, Tc);
        } else {
#pragma unroll
            for (int k = 0; k < 9; ++k) Tc[k] = Rm[k];
        }

        // r = Tc * off[j]  (packed offsets from smem)
        u64 o0 = *(const u64*)&off2[j][0];
        u64 o1 = *(const u64*)&off2[j][1];
        u64 o2 = *(const u64*)&off2[j][2];
        u64 r[3];
#pragma unroll
        for (int i = 0; i < 3; ++i)
            r[i] = fma2(Tc[i*3 + 0], o0, fma2(Tc[i*3 + 1], o1, mul2(Tc[i*3 + 2], o2)));
        if (ps >= 0) {
#pragma unroll
            for (int k = 0; k < 3; ++k) r[k] = add2(r[k], R[ps][k]);
        }

        float dFk = 0.0f;
#pragma unroll
        for (int k = 0; k < 3; ++k) {
            float ry, rx; upk(r[k], ry, rx);
            dFk += fabsf(ry - rx);
        }
        accFk += ws[j] * dFk;

        if (ms >= 0) {
#pragma unroll
            for (int k = 0; k < 9; ++k) T[ms][k] = Tc[k];
#pragma unroll
            for (int k = 0; k < 3; ++k) R[ms][k] = r[k];
        }
    }

    // position loss: channels 96..98
#pragma unroll
    for (int k = 0; k < 3; ++k)
        accPos += fabsf(__ldcs(&ymb[(size_t)(NC - 3 + k) * NT]) -
                        __ldcs(&xmb[(size_t)(NC - 3 + k) * NT]));

    const float cRot = 1.0f / ((float)NB * NT * NJ * 4);
    const float cFk  = 1.0f / ((float)NB * NT * NJ * 3);
    const float cPos = 1.0f / ((float)NB * NT * 3);
    float total = accRot * cRot + accFk * cFk + accPos * cPos;

    // block reduction: warp shuffle, then cross-warp via smem
#pragma unroll
    for (int o = 16; o > 0; o >>= 1)
        total += __shfl_down_sync(0xffffffffu, total, o);

    __shared__ float wsum[TPB / 32];
    if ((tid & 31) == 0) wsum[tid >> 5] = total;
    __syncthreads();
    if (tid == 0) {
        float s = 0.0f;
#pragma unroll
        for (int wgi = 0; wgi < TPB / 32; ++wgi) s += wsum[wgi];
        g_partial[blockIdx.y * gridDim.x + blockIdx.x] = s;
    }
}

__global__ __launch_bounds__(RTPB)
void reduce_final_kernel(float* __restrict__ out)
{
    const int tid = threadIdx.x;
    float s = 0.0f;
#pragma unroll
    for (int k = 0; k < NBLK / RTPB; ++k)
        s += g_partial[tid * (NBLK / RTPB) + k];

#pragma unroll
    for (int o = 16; o > 0; o >>= 1)
        s += __shfl_down_sync(0xffffffffu, s, o);

    __shared__ float wsum[RTPB / 32];
    if ((tid & 31) == 0) wsum[tid >> 5] = s;
    __syncthreads();
    if (tid == 0) {
        float r = 0.0f;
#pragma unroll
        for (int wgi = 0; wgi < RTPB / 32; ++wgi) r += wsum[wgi];
        out[0] = r;
    }
}

extern "C" void kernel_launch(void* const* d_in, const int* in_sizes, int n_in,
                              void* d_out, int out_size)
{
    const float* Ym = (const float*)d_in[0];
    const float* Xm = (const float*)d_in[1];
    const float* Yt = (const float*)d_in[2];
    const float* Xt = (const float*)d_in[3];
    const float* jw = (const float*)d_in[4];

    dim3 grid(GX, NB);
    motion_loss_kernel<<<grid, TPB>>>(Ym, Xm, Yt, Xt, jw);
    reduce_final_kernel<<<1, RTPB>>>((float*)d_out);
}

// round 8
// speedup vs baseline: 1.2866x; 1.2866x over previous
#include <cuda_runtime.h>

// Motion loss: loss_rot + loss_fk + loss_pos.
// B=64, T=2048, J=24, C=4*J+3=99.
//
// R3 scalar design (best measured): one thread per (b,t), both motions in
// registers, 3-slot transform pool from topology liveness. Restructures that
// lost: motion-split+SHFL (MIO bound), packed f32x2 (reg pairs + asm barriers),
// fused threadfence tail (net negative).
// This round: leaf-joint shortcut (skip mm33 for joints never used as parents)
// + PDL so the reduce kernel's launch overlaps the main kernel.

#define NB 64
#define NT 2048
#define NJ 24
#define NC 99

#define TPB 128                    // threads per block (t-chunk)
#define GX  (NT / TPB)             // 16
#define NBLK (GX * NB)             // 1024 partial sums
#define RTPB 256                   // reduce kernel threads

__device__ float g_partial[NBLK];

// Slot assignment (A=0,B=1,C=2) from liveness analysis of the chain.
// PSLOT[j] = pool slot holding transform/result of parent(j)  (-1 for root)
// MSLOT[j] = pool slot to store joint j's transform/result into (-1 if leaf)
#define PSLOT_INIT {-1,0,0,0,1,2,0,1,2,0,1,2,0,0,0,1,2,0,2,0,2,0,2,0}
#define MSLOT_INIT { 0,1,2,0,1,2,0,1,2,0,-1,-1,1,2,0,-1,2,0,2,0,2,0,-1,-1}

__device__ __forceinline__ void quat2mat(float w, float x, float y, float z, float* m)
{
    float s = __fdividef(2.0f, w*w + x*x + y*y + z*z);
    float xx = x*x, yy = y*y, zz = z*z;
    float xy = x*y, xz = x*z, yz = y*z;
    float wx = w*x, wy = w*y, wz = w*z;
    m[0] = 1.0f - s*(yy + zz); m[1] = s*(xy - wz);        m[2] = s*(xz + wy);
    m[3] = s*(xy + wz);        m[4] = 1.0f - s*(xx + zz); m[5] = s*(yz - wx);
    m[6] = s*(xz - wy);        m[7] = s*(yz + wx);        m[8] = 1.0f - s*(xx + yy);
}

__device__ __forceinline__ void mm33(const float* a, const float* b, float* c)
{
#pragma unroll
    for (int i = 0; i < 3; ++i)
#pragma unroll
        for (int j = 0; j < 3; ++j)
            c[i*3 + j] = a[i*3 + 0]*b[0*3 + j] + a[i*3 + 1]*b[1*3 + j] + a[i*3 + 2]*b[2*3 + j];
}

__device__ __forceinline__ void mv3(const float* a, const float* v, float* r)
{
#pragma unroll
    for (int i = 0; i < 3; ++i)
        r[i] = a[i*3 + 0]*v[0] + a[i*3 + 1]*v[1] + a[i*3 + 2]*v[2];
}

__global__ __launch_bounds__(TPB, 4)
void motion_loss_kernel(const float* __restrict__ Ym, const float* __restrict__ Xm,
                        const float* __restrict__ Yt, const float* __restrict__ Xt,
                        const float* __restrict__ jw)
{
    const int b   = blockIdx.y;
    const int tid = threadIdx.x;
    const int t   = blockIdx.x * TPB + tid;

    __shared__ float offY[NJ][3];
    __shared__ float offX[NJ][3];
    __shared__ float ws[NJ];

    if (tid < NJ * 3) {
        offY[tid / 3][tid % 3] = Yt[b * NJ * 3 + tid];
        offX[tid / 3][tid % 3] = Xt[b * NJ * 3 + tid];
    }
    if (tid < NJ) ws[tid] = jw[tid];
    __syncthreads();

    const float* ymb = Ym + (size_t)b * NC * NT + t;
    const float* xmb = Xm + (size_t)b * NC * NT + t;

    float accRot = 0.0f, accFk = 0.0f, accPos = 0.0f;

    // 3-slot register pools (per motion): transforms + world positions
    float Ty[3][9], Tx[3][9];
    float Ry[3][3], Rx[3][3];

    const int PSLOT[NJ] = PSLOT_INIT;
    const int MSLOT[NJ] = MSLOT_INIT;

#pragma unroll
    for (int j = 0; j < NJ; ++j) {
        const int ps = PSLOT[j];
        const int ms = MSLOT[j];

        float qy[4], qx[4];
#pragma unroll
        for (int k = 0; k < 4; ++k) {
            qy[k] = __ldcs(&ymb[(size_t)(4*j + k) * NT]);
            qx[k] = __ldcs(&xmb[(size_t)(4*j + k) * NT]);
        }

        accRot += ws[j] * (fabsf(qy[0]-qx[0]) + fabsf(qy[1]-qx[1]) +
                           fabsf(qy[2]-qx[2]) + fabsf(qy[3]-qx[3]));

        float Ra[9], Rb[9];
        quat2mat(qy[0], qy[1], qy[2], qy[3], Ra);
        quat2mat(qx[0], qx[1], qx[2], qx[3], Rb);

        float ry[3], rx[3];

        if (ms < 0 && ps >= 0) {
            // Leaf joint: never used as a parent -> skip full mm33.
            // r = T[ps] * (Rm * off) + R[ps]   (18 FMA instead of 36)
            float ly[3], lx[3];
            mv3(Ra, &offY[j][0], ly);
            mv3(Rb, &offX[j][0], lx);
            mv3(Ty[ps], ly, ry);
            mv3(Tx[ps], lx, rx);
#pragma unroll
            for (int k = 0; k < 3; ++k) { ry[k] += Ry[ps][k]; rx[k] += Rx[ps][k]; }
        } else {
            float Tyc[9], Txc[9];
            if (ps >= 0) {
                mm33(Ty[ps], Ra, Tyc);
                mm33(Tx[ps], Rb, Txc);
            } else {
#pragma unroll
                for (int k = 0; k < 9; ++k) { Tyc[k] = Ra[k]; Txc[k] = Rb[k]; }
            }

            mv3(Tyc, &offY[j][0], ry);
            mv3(Txc, &offX[j][0], rx);
            if (ps >= 0) {
#pragma unroll
                for (int k = 0; k < 3; ++k) { ry[k] += Ry[ps][k]; rx[k] += Rx[ps][k]; }
            }

            if (ms >= 0) {
#pragma unroll
                for (int k = 0; k < 9; ++k) { Ty[ms][k] = Tyc[k]; Tx[ms][k] = Txc[k]; }
#pragma unroll
                for (int k = 0; k < 3; ++k) { Ry[ms][k] = ry[k];  Rx[ms][k] = rx[k]; }
            }
        }

        accFk += ws[j] * (fabsf(ry[0]-rx[0]) + fabsf(ry[1]-rx[1]) + fabsf(ry[2]-rx[2]));
    }

    // position loss: channels 96..98
#pragma unroll
    for (int k = 0; k < 3; ++k)
        accPos += fabsf(__ldcs(&ymb[(size_t)(NC - 3 + k) * NT]) -
                        __ldcs(&xmb[(size_t)(NC - 3 + k) * NT]));

    const float cRot = 1.0f / ((float)NB * NT * NJ * 4);
    const float cFk  = 1.0f / ((float)NB * NT * NJ * 3);
    const float cPos = 1.0f / ((float)NB * NT * 3);
    float total = accRot * cRot + accFk * cFk + accPos * cPos;

    // block reduction: warp shuffle, then cross-warp via smem
#pragma unroll
    for (int o = 16; o > 0; o >>= 1)
        total += __shfl_down_sync(0xffffffffu, total, o);

    __shared__ float wsum[TPB / 32];
    if ((tid & 31) == 0) wsum[tid >> 5] = total;
    __syncthreads();
    if (tid == 0) {
        float s = 0.0f;
#pragma unroll
        for (int wgi = 0; wgi < TPB / 32; ++wgi) s += wsum[wgi];
        g_partial[blockIdx.y * gridDim.x + blockIdx.x] = s;
        __threadfence();
        // PDL: this CTA's partial is published; allow dependent grid launch.
        asm volatile("griddepcontrol.launch_dependents;");
    }
}

__global__ __launch_bounds__(RTPB)
void reduce_final_kernel(float* __restrict__ out)
{
    // PDL: wait until all primary CTAs have published their partials.
    asm volatile("griddepcontrol.wait;");

    const int tid = threadIdx.x;
    float s = 0.0f;
#pragma unroll
    for (int k = 0; k < NBLK / RTPB; ++k)
        s += __ldcg(&g_partial[tid * (NBLK / RTPB) + k]);

#pragma unroll
    for (int o = 16; o > 0; o >>= 1)
        s += __shfl_down_sync(0xffffffffu, s, o);

    __shared__ float wsum[RTPB / 32];
    if ((tid & 31) == 0) wsum[tid >> 5] = s;
    __syncthreads();
    if (tid == 0) {
        float r = 0.0f;
#pragma unroll
        for (int wgi = 0; wgi < RTPB / 32; ++wgi) r += wsum[wgi];
        out[0] = r;
    }
}

extern "C" void kernel_launch(void* const* d_in, const int* in_sizes, int n_in,
                              void* d_out, int out_size)
{
    const float* Ym = (const float*)d_in[0];
    const float* Xm = (const float*)d_in[1];
    const float* Yt = (const float*)d_in[2];
    const float* Xt = (const float*)d_in[3];
    const float* jw = (const float*)d_in[4];

    dim3 grid(GX, NB);
    motion_loss_kernel<<<grid, TPB>>>(Ym, Xm, Yt, Xt, jw);

    // Reduce kernel with programmatic dependent launch: its launch overlaps
    // the primary's execution; griddepcontrol.wait provides the ordering.
    cudaLaunchConfig_t cfg = {};
    cfg.gridDim  = dim3(1, 1, 1);
    cfg.blockDim = dim3(RTPB, 1, 1);
    cudaLaunchAttribute attr[1];
    attr[0].id = cudaLaunchAttributeProgrammaticStreamSerialization;
    attr[0].val.programmaticStreamSerializationAllowed = 1;
    cfg.attrs = attr;
    cfg.numAttrs = 1;
    cudaLaunchKernelEx(&cfg, reduce_final_kernel, (float*)d_out);
}

// round 14
// speedup vs baseline: 1.3586x; 1.0559x over previous
#include <cuda_runtime.h>

// Motion loss: loss_rot + loss_fk + loss_pos.
// B=64, T=2048, J=24, C=4*J+3=99.
//
// R3 body VERBATIM (best measured: 24.9us main + 4.26us reduce = 29.2us).
// Restructures that lost and are banned: motion-split+SHFL (33.2), packed
// f32x2 (39.6), fused threadfence tail (30.8), leaf-shortcut+PDL (30.8).
// This round's SINGLE change: PDL (programmatic dependent launch) so the
// reduce kernel's launch overlaps the main kernel's drain.

#define NB 64
#define NT 2048
#define NJ 24
#define NC 99

#define TPB 128                    // threads per block (t-chunk)
#define GX  (NT / TPB)             // 16
#define NBLK (GX * NB)             // 1024 partial sums

__device__ float g_partial[NBLK];

// Slot assignment (A=0,B=1,C=2) from liveness analysis of the chain.
// PSLOT[j] = pool slot holding transform/result of parent(j)  (-1 for root)
// MSLOT[j] = pool slot to store joint j's transform/result into (-1 if leaf)
#define PSLOT_INIT {-1,0,0,0,1,2,0,1,2,0,1,2,0,0,0,1,2,0,2,0,2,0,2,0}
#define MSLOT_INIT { 0,1,2,0,1,2,0,1,2,0,-1,-1,1,2,0,-1,2,0,2,0,2,0,-1,-1}

__device__ __forceinline__ void quat2mat(float w, float x, float y, float z, float* m)
{
    float s = __fdividef(2.0f, w*w + x*x + y*y + z*z);
    float xx = x*x, yy = y*y, zz = z*z;
    float xy = x*y, xz = x*z, yz = y*z;
    float wx = w*x, wy = w*y, wz = w*z;
    m[0] = 1.0f - s*(yy + zz); m[1] = s*(xy - wz);        m[2] = s*(xz + wy);
    m[3] = s*(xy + wz);        m[4] = 1.0f - s*(xx + zz); m[5] = s*(yz - wx);
    m[6] = s*(xz - wy);        m[7] = s*(yz + wx);        m[8] = 1.0f - s*(xx + yy);
}

__device__ __forceinline__ void mm33(const float* a, const float* b, float* c)
{
#pragma unroll
    for (int i = 0; i < 3; ++i)
#pragma unroll
        for (int j = 0; j < 3; ++j)
            c[i*3 + j] = a[i*3 + 0]*b[0*3 + j] + a[i*3 + 1]*b[1*3 + j] + a[i*3 + 2]*b[2*3 + j];
}

__device__ __forceinline__ void mv3(const float* a, const float* v, float* r)
{
#pragma unroll
    for (int i = 0; i < 3; ++i)
        r[i] = a[i*3 + 0]*v[0] + a[i*3 + 1]*v[1] + a[i*3 + 2]*v[2];
}

__global__ __launch_bounds__(TPB)
void motion_loss_kernel(const float* __restrict__ Ym, const float* __restrict__ Xm,
                        const float* __restrict__ Yt, const float* __restrict__ Xt,
                        const float* __restrict__ jw)
{
    const int b   = blockIdx.y;
    const int tid = threadIdx.x;
    const int t   = blockIdx.x * TPB + tid;

    __shared__ float offY[NJ][3];
    __shared__ float offX[NJ][3];
    __shared__ float ws[NJ];

    if (tid < NJ * 3) {
        offY[tid / 3][tid % 3] = Yt[b * NJ * 3 + tid];
        offX[tid / 3][tid % 3] = Xt[b * NJ * 3 + tid];
    }
    if (tid < NJ) ws[tid] = jw[tid];
    __syncthreads();

    const float* ymb = Ym + (size_t)b * NC * NT + t;
    const float* xmb = Xm + (size_t)b * NC * NT + t;

    float accRot = 0.0f, accFk = 0.0f, accPos = 0.0f;

    // 3-slot register pools (per motion): transforms + world positions
    float Ty[3][9], Tx[3][9];
    float Ry[3][3], Rx[3][3];

    const int PSLOT[NJ] = PSLOT_INIT;
    const int MSLOT[NJ] = MSLOT_INIT;

#pragma unroll
    for (int j = 0; j < NJ; ++j) {
        const int ps = PSLOT[j];
        const int ms = MSLOT[j];

        float qy[4], qx[4];
#pragma unroll
        for (int k = 0; k < 4; ++k) {
            qy[k] = __ldcs(&ymb[(size_t)(4*j + k) * NT]);
            qx[k] = __ldcs(&xmb[(size_t)(4*j + k) * NT]);
        }

        accRot += ws[j] * (fabsf(qy[0]-qx[0]) + fabsf(qy[1]-qx[1]) +
                           fabsf(qy[2]-qx[2]) + fabsf(qy[3]-qx[3]));

        float Ra[9], Rb[9];
        quat2mat(qy[0], qy[1], qy[2], qy[3], Ra);
        quat2mat(qx[0], qx[1], qx[2], qx[3], Rb);

        float Tyc[9], Txc[9];
        if (ps >= 0) {
            mm33(Ty[ps], Ra, Tyc);
            mm33(Tx[ps], Rb, Txc);
        } else {
#pragma unroll
            for (int k = 0; k < 9; ++k) { Tyc[k] = Ra[k]; Txc[k] = Rb[k]; }
        }

        float ry[3], rx[3];
        mv3(Tyc, &offY[j][0], ry);
        mv3(Txc, &offX[j][0], rx);
        if (ps >= 0) {
#pragma unroll
            for (int k = 0; k < 3; ++k) { ry[k] += Ry[ps][k]; rx[k] += Rx[ps][k]; }
        }

        accFk += ws[j] * (fabsf(ry[0]-rx[0]) + fabsf(ry[1]-rx[1]) + fabsf(ry[2]-rx[2]));

        if (ms >= 0) {
#pragma unroll
            for (int k = 0; k < 9; ++k) { Ty[ms][k] = Tyc[k]; Tx[ms][k] = Txc[k]; }
#pragma unroll
            for (int k = 0; k < 3; ++k) { Ry[ms][k] = ry[k];  Rx[ms][k] = rx[k]; }
        }
    }

    // position loss: channels 96..98
#pragma unroll
    for (int k = 0; k < 3; ++k)
        accPos += fabsf(__ldcs(&ymb[(size_t)(NC - 3 + k) * NT]) -
                        __ldcs(&xmb[(size_t)(NC - 3 + k) * NT]));

    const float cRot = 1.0f / ((float)NB * NT * NJ * 4);
    const float cFk  = 1.0f / ((float)NB * NT * NJ * 3);
    const float cPos = 1.0f / ((float)NB * NT * 3);
    float total = accRot * cRot + accFk * cFk + accPos * cPos;

    // deterministic block reduction: warp shuffle, then cross-warp via smem
#pragma unroll
    for (int off = 16; off > 0; off >>= 1)
        total += __shfl_down_sync(0xffffffffu, total, off);

    __shared__ float wsum[TPB / 32];
    if ((tid & 31) == 0) wsum[tid >> 5] = total;
    __syncthreads();
    if (tid == 0) {
        float s = 0.0f;
#pragma unroll
        for (int wgi = 0; wgi < TPB / 32; ++wgi) s += wsum[wgi];
        g_partial[blockIdx.y * gridDim.x + blockIdx.x] = s;
        __threadfence();
        // PDL: this CTA's partial is published; allow the dependent grid.
        asm volatile("griddepcontrol.launch_dependents;");
    }
}

__global__ __launch_bounds__(NBLK)
void reduce_final_kernel(float* __restrict__ out)
{
    // PDL: block until every primary CTA has executed launch_dependents
    // (i.e., all partials are published).
    asm volatile("griddepcontrol.wait;");

    __shared__ float s[NBLK];
    const int tid = threadIdx.x;
    s[tid] = __ldcg(&g_partial[tid]);
    __syncthreads();
#pragma unroll
    for (int st = NBLK / 2; st > 0; st >>= 1) {
        if (tid < st) s[tid] += s[tid + st];
        __syncthreads();
    }
    if (tid == 0) out[0] = s[0];
}

extern "C" void kernel_launch(void* const* d_in, const int* in_sizes, int n_in,
                              void* d_out, int out_size)
{
    const float* Ym = (const float*)d_in[0];
    const float* Xm = (const float*)d_in[1];
    const float* Yt = (const float*)d_in[2];
    const float* Xt = (const float*)d_in[3];
    const float* jw = (const float*)d_in[4];

    dim3 grid(GX, NB);
    motion_loss_kernel<<<grid, TPB>>>(Ym, Xm, Yt, Xt, jw);

    // Reduce with programmatic dependent launch: launch setup overlaps the
    // primary kernel; griddepcontrol.wait provides the data ordering.
    cudaLaunchConfig_t cfg = {};
    cfg.gridDim  = dim3(1, 1, 1);
    cfg.blockDim = dim3(NBLK, 1, 1);
    cudaLaunchAttribute attr[1];
    attr[0].id = cudaLaunchAttributeProgrammaticStreamSerialization;
    attr[0].val.programmaticStreamSerializationAllowed = 1;
    cfg.attrs = attr;
    cfg.numAttrs = 1;
    cudaLaunchKernelEx(&cfg, reduce_final_kernel, (float*)d_out);
}